// round 6
// baseline (speedup 1.0000x reference)
#include <cuda_runtime.h>

#define NWIRES  12
#define DIM     4096
#define NLAYERS 4
#define NT      256

// dynamic smem layout (bytes)
//  st  : 2*DIM float2          = 65536
//  Ug  : 2*48 float4           = 1536
//  red : 2*64 float            = 512
#define SMEM_TOTAL (2*DIM*8 + 2*48*16 + 2*64*4)

__device__ __forceinline__ float2 cmul(float2 a, float2 b) {
    return make_float2(fmaf(a.x, b.x, -(a.y * b.y)),
                       fmaf(a.x, b.y,   a.y * b.x));
}
__device__ __forceinline__ float2 cfma(float2 a, float2 b, float2 c) {
    c.x = fmaf(a.x, b.x, fmaf(-a.y, b.y, c.x));
    c.y = fmaf(a.x, b.y, fmaf( a.y, b.x, c.y));
    return c;
}

// bank-conflict-avoiding swizzle: XOR low 4 bits with bits 4-7
__device__ __forceinline__ int saddr(int j) { return j ^ ((j >> 4) & 15); }

// h = g^{-1} (prefix-XOR) of the CNOT-chain permutation, then swizzle
__device__ __forceinline__ int haddr(int j) {
    j ^= j >> 1; j ^= j >> 2; j ^= j >> 4; j ^= j >> 8;
    return saddr(j);
}

// logical index owned by thread t, local slot v, for round R
template <int R>
__device__ __forceinline__ int jidx(int t, int v) {
    if (R == 0) return (t << 4) | v;
    if (R == 1) return ((t & 0xF0) << 4) | (v << 4) | (t & 15);
    return (v << 8) | t;
}

// SU(2) butterfly: g = (u00r, u00i, u01r, u01i); u10=-conj(u01), u11=conj(u00)
__device__ __forceinline__ void bfly(float4 g, float& r0, float& i0, float& r1, float& i1) {
    const float a = r0, b = i0, c = r1, d = i1;
    r0 = fmaf( g.x, a, fmaf(-g.y, b, fmaf( g.z, c, -(g.w * d))));
    i0 = fmaf( g.y, a, fmaf( g.x, b, fmaf( g.w, c,   g.z * d)));
    r1 = fmaf(-g.z, a, fmaf(-g.w, b, fmaf( g.x, c,   g.y * d)));
    i1 = fmaf( g.w, a, fmaf(-g.z, b, fmaf(-g.y, c,   g.x * d)));
}

// gather 16 amps of BOTH states; apply this round's 4 gates in registers
template <int R>
__device__ __forceinline__ void gather_apply2(const float2* __restrict__ st,
                                              const float4* __restrict__ Ug,
                                              int L, int t,
                                              float* reA, float* imA,
                                              float* reB, float* imB) {
    #pragma unroll
    for (int v = 0; v < 16; ++v) {
        const int adr = saddr(jidx<R>(t, v));
        const float2 a = st[adr];
        const float2 b = st[DIM + adr];
        reA[v] = a.x; imA[v] = a.y;
        reB[v] = b.x; imB[v] = b.y;
    }
    #pragma unroll
    for (int lb = 0; lb < 4; ++lb) {
        const int wi = 11 - (4 * R + lb);
        const float4 gA = Ug[L * NWIRES + wi];
        const float4 gB = Ug[48 + L * NWIRES + wi];
        const int str = 1 << lb;
        #pragma unroll
        for (int p = 0; p < 8; ++p) {
            const int i0 = ((p & ~(str - 1)) << 1) | (p & (str - 1));
            const int i1 = i0 | str;
            bfly(gA, reA[i0], imA[i0], reA[i1], imA[i1]);
            bfly(gB, reB[i0], imB[i0], reB[i1], imB[i1]);
        }
    }
}

__global__ __launch_bounds__(NT, 2)
void qnn_kernel(const float* __restrict__ x, const float* __restrict__ w,
                float* __restrict__ out)
{
    extern __shared__ char smem[];
    float2* st  = (float2*)smem;                      // [2*DIM]
    float4* Ug  = (float4*)(smem + 2 * DIM * 8);      // [2*48]
    float*  red = (float*)(smem + 2 * DIM * 8 + 2 * 48 * 16);  // [2*64]

    const int b0 = blockIdx.x * 2;
    const int t  = threadIdx.x;

    // ---- build fused SU(2) gates U = RZ RY RX @ Enc for both elements (96 thr)
    if (t < 2 * NLAYERS * NWIRES) {
        const int e = t / 48, idx = t % 48;
        const int l = idx / NWIRES, wi = idx % NWIRES;
        const float* wp = w + (l * NWIRES + wi) * 3;
        float sa, ca, sb, cb, sg, cg;
        sincosf(0.5f * wp[0], &sa, &ca);
        sincosf(0.5f * wp[1], &sb, &cb);
        sincosf(0.5f * wp[2], &sg, &cg);
        float2 m00 = make_float2( cb * ca,  sb * sa);
        float2 m01 = make_float2(-sb * ca, -cb * sa);
        float2 m10 = make_float2( sb * ca, -cb * sa);
        float2 m11 = make_float2( cb * ca, -sb * sa);
        const float2 e0 = make_float2(cg, -sg);
        const float2 e1 = make_float2(cg,  sg);
        m00 = cmul(e0, m00); m01 = cmul(e0, m01);
        m10 = cmul(e1, m10); m11 = cmul(e1, m11);
        const float th = x[(b0 + e) * 2 + (wi & 1)];
        float se, ce;
        sincosf(0.5f * th, &se, &ce);
        float2 E00, E01, E10, E11;
        if (wi & 1) { // RY
            E00 = make_float2(ce, 0.f);  E01 = make_float2(-se, 0.f);
            E10 = make_float2(se, 0.f);  E11 = make_float2(ce, 0.f);
        } else {      // RX
            E00 = make_float2(ce, 0.f);  E01 = make_float2(0.f, -se);
            E10 = make_float2(0.f, -se); E11 = make_float2(ce, 0.f);
        }
        const float2 u00 = cfma(m01, E10, cmul(m00, E00));
        const float2 u01 = cfma(m01, E11, cmul(m00, E01));
        Ug[e * 48 + idx] = make_float4(u00.x, u00.y, u01.x, u01.y);
    }
    __syncthreads();

    // ---- layer 0 on |0..0>: product state, stored through CNOT map h ----
    #pragma unroll
    for (int e = 0; e < 2; ++e) {
        const float4* U = Ug + e * 48;
        float pre = 1.f, pim = 0.f;
        #pragma unroll
        for (int bit = 0; bit < 8; ++bit) {
            const int row = (t >> bit) & 1;
            const float4 g = U[11 - bit];
            // column 0, row r: r=0 -> (g.x,g.y) ; r=1 -> (-g.z, g.w)
            const float cr = row ? -g.z : g.x;
            const float ci = row ?  g.w : g.y;
            const float nre = fmaf(cr, pre, -(ci * pim));
            const float nim = fmaf(ci, pre,   cr * pim);
            pre = nre; pim = nim;
        }
        #pragma unroll
        for (int v = 0; v < 16; ++v) {
            float vre = pre, vim = pim;
            #pragma unroll
            for (int bit = 0; bit < 4; ++bit) {
                const int row = (v >> bit) & 1;
                const float4 g = U[3 - bit];
                const float cr = row ? -g.z : g.x;
                const float ci = row ?  g.w : g.y;
                const float nre = fmaf(cr, vre, -(ci * vim));
                const float nim = fmaf(ci, vre,   cr * vim);
                vre = nre; vim = nim;
            }
            st[e * DIM + haddr((v << 8) | t)] = make_float2(vre, vim);
        }
    }
    __syncthreads();

    float reA[16], imA[16], reB[16], imB[16];

    // ---- layers 1..2: 3 rounds each, last round scatters through h ----
    for (int L = 1; L <= 2; ++L) {
        gather_apply2<0>(st, Ug, L, t, reA, imA, reB, imB);
        #pragma unroll
        for (int v = 0; v < 16; ++v) {
            const int adr = saddr(jidx<0>(t, v));
            st[adr]       = make_float2(reA[v], imA[v]);
            st[DIM + adr] = make_float2(reB[v], imB[v]);
        }
        __syncthreads();
        gather_apply2<1>(st, Ug, L, t, reA, imA, reB, imB);
        #pragma unroll
        for (int v = 0; v < 16; ++v) {
            const int adr = saddr(jidx<1>(t, v));
            st[adr]       = make_float2(reA[v], imA[v]);
            st[DIM + adr] = make_float2(reB[v], imB[v]);
        }
        __syncthreads();
        gather_apply2<2>(st, Ug, L, t, reA, imA, reB, imB);
        #pragma unroll
        for (int v = 0; v < 16; ++v) {
            const int adr = haddr(jidx<2>(t, v));
            st[adr]       = make_float2(reA[v], imA[v]);
            st[DIM + adr] = make_float2(reB[v], imB[v]);
        }
        __syncthreads();
    }

    // ---- layer 3: rounds 0,1 as usual; round 2 fused with measurement ----
    {
        gather_apply2<0>(st, Ug, 3, t, reA, imA, reB, imB);
        #pragma unroll
        for (int v = 0; v < 16; ++v) {
            const int adr = saddr(jidx<0>(t, v));
            st[adr]       = make_float2(reA[v], imA[v]);
            st[DIM + adr] = make_float2(reB[v], imB[v]);
        }
        __syncthreads();
        gather_apply2<1>(st, Ug, 3, t, reA, imA, reB, imB);
        #pragma unroll
        for (int v = 0; v < 16; ++v) {
            const int adr = saddr(jidx<1>(t, v));
            st[adr]       = make_float2(reA[v], imA[v]);
            st[DIM + adr] = make_float2(reB[v], imB[v]);
        }
        __syncthreads();
        gather_apply2<2>(st, Ug, 3, t, reA, imA, reB, imB);
    }

    // ---- measurement straight from registers, both elements ----
    const int t7 = (t >> 7) & 1, t6 = (t >> 6) & 1, t5 = (t >> 5) & 1, t4 = (t >> 4) & 1;
    const unsigned FULL = 0xffffffffu;
    #pragma unroll
    for (int e = 0; e < 2; ++e) {
        const float* re = e ? reB : reA;
        const float* im = e ? imB : imA;
        float acc0 = 0.f, acc1 = 0.f, acc2 = 0.f, se = 0.f, so = 0.f;
        #pragma unroll
        for (int v = 0; v < 16; ++v) {
            const float p = fmaf(re[v], re[v], im[v] * im[v]);
            const int b3 = (v >> 3) & 1, b2 = (v >> 2) & 1, b1 = (v >> 1) & 1, bb = v & 1;
            acc0 += b3 ? -p : p;
            acc1 += (b3 ^ b2) ? -p : p;
            acc2 += (b3 ^ b2 ^ b1) ? -p : p;
            if (b3 ^ b2 ^ b1 ^ bb) so += p; else se += p;
        }
        const float d = se - so;
        float rr[8];
        rr[0] = acc0; rr[1] = acc1; rr[2] = acc2; rr[3] = d;
        rr[4] = t7 ? -d : d;
        rr[5] = (t7 ^ t6) ? -d : d;
        rr[6] = (t7 ^ t6 ^ t5) ? -d : d;
        rr[7] = (t7 ^ t6 ^ t5 ^ t4) ? -d : d;
        #pragma unroll
        for (int i = 0; i < 8; ++i) {
            float v = rr[i];
            #pragma unroll
            for (int o = 16; o > 0; o >>= 1) v += __shfl_xor_sync(FULL, v, o);
            if ((t & 31) == 0) red[e * 64 + (t >> 5) * 8 + i] = v;
        }
    }
    __syncthreads();
    if (t < 16) {
        const int e = t >> 3, i = t & 7;
        float s = 0.f;
        #pragma unroll
        for (int wp2 = 0; wp2 < 8; ++wp2) s += red[e * 64 + wp2 * 8 + i];
        out[(b0 + e) * 8 + i] = s * 3.14159265358979f;
    }
}

extern "C" void kernel_launch(void* const* d_in, const int* in_sizes, int n_in,
                              void* d_out, int out_size) {
    const float* x = (const float*)d_in[0];   // [B, 2]
    const float* w = (const float*)d_in[1];   // [4, 12, 3]
    float* out = (float*)d_out;               // [B, 8]
    const int B = in_sizes[0] / 2;
    cudaFuncSetAttribute(qnn_kernel, cudaFuncAttributeMaxDynamicSharedMemorySize, SMEM_TOTAL);
    qnn_kernel<<<B / 2, NT, SMEM_TOTAL>>>(x, w, out);
}

// round 7
// speedup vs baseline: 1.0829x; 1.0829x over previous
#include <cuda_runtime.h>

#define NWIRES  12
#define DIM     4096
#define NLAYERS 4
#define NT      256

__device__ __forceinline__ float2 cmul(float2 a, float2 b) {
    return make_float2(fmaf(a.x, b.x, -(a.y * b.y)),
                       fmaf(a.x, b.y,   a.y * b.x));
}
__device__ __forceinline__ float2 cfma(float2 a, float2 b, float2 c) {
    c.x = fmaf(a.x, b.x, fmaf(-a.y, b.y, c.x));
    c.y = fmaf(a.x, b.y, fmaf( a.y, b.x, c.y));
    return c;
}

// bank-conflict-avoiding swizzle: XOR low 4 bits with bits 4-7
__device__ __forceinline__ int saddr(int j) { return j ^ ((j >> 4) & 15); }

// h = g^{-1} (prefix-XOR) of the CNOT-chain permutation, then swizzle
__device__ __forceinline__ int haddr(int j) {
    j ^= j >> 1; j ^= j >> 2; j ^= j >> 4; j ^= j >> 8;
    return saddr(j);
}

// logical index owned by thread t, local slot v, for round R
template <int R>
__device__ __forceinline__ int jidx(int t, int v) {
    if (R == 0) return (t << 4) | v;
    if (R == 1) return ((t & 0xF0) << 4) | (v << 4) | (t & 15);
    return (v << 8) | t;
}

// SU(2) butterfly, STAGED by shared multiplicand for RF-bank operand reuse.
// g = (u00r, u00i, u01r, u01i); u10 = -conj(u01), u11 = conj(u00).
//   r0' =  gx a - gy b + gz c - gw d
//   i0' =  gy a + gx b + gw c + gz d
//   r1' = -gz a - gw b + gx c + gy d
//   i1' =  gw a - gz b - gy c + gx d
__device__ __forceinline__ void bfly(float4 g, float& r0, float& i0, float& r1, float& i1) {
    const float a = r0, b = i0, c = r1, d = i1;
    float n0 =  g.x * a;
    float n1 =  g.y * a;
    float n2 = -g.z * a;
    float n3 =  g.w * a;
    n0 = fmaf(-g.y, b, n0);
    n1 = fmaf( g.x, b, n1);
    n2 = fmaf(-g.w, b, n2);
    n3 = fmaf(-g.z, b, n3);
    n0 = fmaf( g.z, c, n0);
    n1 = fmaf( g.w, c, n1);
    n2 = fmaf( g.x, c, n2);
    n3 = fmaf(-g.y, c, n3);
    n0 = fmaf(-g.w, d, n0);
    n1 = fmaf( g.z, d, n1);
    n2 = fmaf( g.y, d, n2);
    n3 = fmaf( g.x, d, n3);
    r0 = n0; i0 = n1; r1 = n2; i1 = n3;
}

// gather 16 amps; apply this round's 4 gates in registers
template <int R>
__device__ __forceinline__ void gather_apply(const float2* __restrict__ st,
                                             const float4* __restrict__ Ug,
                                             int L, int t,
                                             float* re, float* im) {
    #pragma unroll
    for (int v = 0; v < 16; ++v) {
        const float2 a = st[saddr(jidx<R>(t, v))];
        re[v] = a.x; im[v] = a.y;
    }
    #pragma unroll
    for (int lb = 0; lb < 4; ++lb) {
        const int wi = 11 - (4 * R + lb);
        const float4 g = Ug[L * NWIRES + wi];
        const int str = 1 << lb;
        #pragma unroll
        for (int p = 0; p < 8; ++p) {
            const int i0 = ((p & ~(str - 1)) << 1) | (p & (str - 1));
            const int i1 = i0 | str;
            bfly(g, re[i0], im[i0], re[i1], im[i1]);
        }
    }
}

__global__ __launch_bounds__(NT, 3)
void qnn_kernel(const float* __restrict__ x, const float* __restrict__ w,
                float* __restrict__ out)
{
    __shared__ float2 st[DIM];                    // 32 KB state (swizzled)
    __shared__ float4 Ug[NLAYERS * NWIRES];       // SU(2) gates: 1 float4 each
    __shared__ float  red[8 * 8];

    const int b = blockIdx.x;
    const int t = threadIdx.x;

    // ---- build fused SU(2) gates U = RZ RY RX @ Enc (48 threads) ----
    if (t < NLAYERS * NWIRES) {
        const int l = t / NWIRES, wi = t % NWIRES;
        const float* wp = w + (l * NWIRES + wi) * 3;
        float sa, ca, sb, cb, sg, cg;
        sincosf(0.5f * wp[0], &sa, &ca);
        sincosf(0.5f * wp[1], &sb, &cb);
        sincosf(0.5f * wp[2], &sg, &cg);
        float2 m00 = make_float2( cb * ca,  sb * sa);
        float2 m01 = make_float2(-sb * ca, -cb * sa);
        const float2 e0 = make_float2(cg, -sg);
        m00 = cmul(e0, m00); m01 = cmul(e0, m01);
        const float th = x[b * 2 + (wi & 1)];
        float se, ce;
        sincosf(0.5f * th, &se, &ce);
        float2 E00, E01, E10, E11;
        if (wi & 1) { // RY
            E00 = make_float2(ce, 0.f);  E01 = make_float2(-se, 0.f);
            E10 = make_float2(se, 0.f);  E11 = make_float2(ce, 0.f);
        } else {      // RX
            E00 = make_float2(ce, 0.f);  E01 = make_float2(0.f, -se);
            E10 = make_float2(0.f, -se); E11 = make_float2(ce, 0.f);
        }
        const float2 u00 = cfma(m01, E10, cmul(m00, E00));
        const float2 u01 = cfma(m01, E11, cmul(m00, E01));
        Ug[t] = make_float4(u00.x, u00.y, u01.x, u01.y);
    }
    __syncthreads();

    // ---- layer 0 on |0..0>: product state, stored through CNOT map h ----
    {
        float pre = 1.f, pim = 0.f;
        #pragma unroll
        for (int bit = 0; bit < 8; ++bit) {
            const int row = (t >> bit) & 1;
            const float4 g = Ug[11 - bit];
            // column 0: row0 -> (g.x, g.y) ; row1 -> u10 = (-g.z, g.w)
            const float cr = row ? -g.z : g.x;
            const float ci = row ?  g.w : g.y;
            const float nre = fmaf(cr, pre, -(ci * pim));
            const float nim = fmaf(ci, pre,   cr * pim);
            pre = nre; pim = nim;
        }
        #pragma unroll
        for (int v = 0; v < 16; ++v) {
            float vre = pre, vim = pim;
            #pragma unroll
            for (int bit = 0; bit < 4; ++bit) {
                const int row = (v >> bit) & 1;
                const float4 g = Ug[3 - bit];
                const float cr = row ? -g.z : g.x;
                const float ci = row ?  g.w : g.y;
                const float nre = fmaf(cr, vre, -(ci * vim));
                const float nim = fmaf(ci, vre,   cr * vim);
                vre = nre; vim = nim;
            }
            st[haddr((v << 8) | t)] = make_float2(vre, vim);
        }
    }
    __syncthreads();

    float re[16], im[16];

    // ---- layers 1..2: 3 rounds each; round0->round1 exchange is warp-local ----
    for (int L = 1; L <= 2; ++L) {
        gather_apply<0>(st, Ug, L, t, re, im);
        #pragma unroll
        for (int v = 0; v < 16; ++v) st[saddr(jidx<0>(t, v))] = make_float2(re[v], im[v]);
        __syncwarp();                                   // 16-group exchange: same warp
        gather_apply<1>(st, Ug, L, t, re, im);
        #pragma unroll
        for (int v = 0; v < 16; ++v) st[saddr(jidx<1>(t, v))] = make_float2(re[v], im[v]);
        __syncthreads();
        gather_apply<2>(st, Ug, L, t, re, im);
        #pragma unroll
        for (int v = 0; v < 16; ++v) st[haddr(jidx<2>(t, v))] = make_float2(re[v], im[v]);
        __syncthreads();
    }

    // ---- layer 3: rounds 0,1; round 2 fused with measurement ----
    {
        gather_apply<0>(st, Ug, 3, t, re, im);
        #pragma unroll
        for (int v = 0; v < 16; ++v) st[saddr(jidx<0>(t, v))] = make_float2(re[v], im[v]);
        __syncwarp();
        gather_apply<1>(st, Ug, 3, t, re, im);
        #pragma unroll
        for (int v = 0; v < 16; ++v) st[saddr(jidx<1>(t, v))] = make_float2(re[v], im[v]);
        __syncthreads();
        gather_apply<2>(st, Ug, 3, t, re, im);
    }

    // ---- measurement straight from registers ----
    float acc0 = 0.f, acc1 = 0.f, acc2 = 0.f, se = 0.f, so = 0.f;
    #pragma unroll
    for (int v = 0; v < 16; ++v) {
        const float p = fmaf(re[v], re[v], im[v] * im[v]);
        const int b3 = (v >> 3) & 1, b2 = (v >> 2) & 1, b1 = (v >> 1) & 1, b0 = v & 1;
        acc0 += b3 ? -p : p;
        acc1 += (b3 ^ b2) ? -p : p;
        acc2 += (b3 ^ b2 ^ b1) ? -p : p;
        if (b3 ^ b2 ^ b1 ^ b0) so += p; else se += p;
    }
    const float d = se - so;
    const int t7 = (t >> 7) & 1, t6 = (t >> 6) & 1, t5 = (t >> 5) & 1, t4 = (t >> 4) & 1;
    float rr[8];
    rr[0] = acc0; rr[1] = acc1; rr[2] = acc2; rr[3] = d;
    rr[4] = t7 ? -d : d;
    rr[5] = (t7 ^ t6) ? -d : d;
    rr[6] = (t7 ^ t6 ^ t5) ? -d : d;
    rr[7] = (t7 ^ t6 ^ t5 ^ t4) ? -d : d;

    const unsigned FULL = 0xffffffffu;
    #pragma unroll
    for (int i = 0; i < 8; ++i) {
        float v = rr[i];
        #pragma unroll
        for (int o = 16; o > 0; o >>= 1) v += __shfl_xor_sync(FULL, v, o);
        if ((t & 31) == 0) red[(t >> 5) * 8 + i] = v;
    }
    __syncthreads();
    if (t < 8) {
        float s = 0.f;
        #pragma unroll
        for (int wp2 = 0; wp2 < 8; ++wp2) s += red[wp2 * 8 + t];
        out[b * 8 + t] = s * 3.14159265358979f;
    }
}

extern "C" void kernel_launch(void* const* d_in, const int* in_sizes, int n_in,
                              void* d_out, int out_size) {
    const float* x = (const float*)d_in[0];   // [B, 2]
    const float* w = (const float*)d_in[1];   // [4, 12, 3]
    float* out = (float*)d_out;               // [B, 8]
    const int B = in_sizes[0] / 2;
    qnn_kernel<<<B, NT>>>(x, w, out);
}